// round 1
// baseline (speedup 1.0000x reference)
#include <cuda_runtime.h>
#include <cuda_bf16.h>

// time_embeddings: out[b, i] = sin/cos(time[b] * 10000^(-(i//2)/640))
// B = 65536 (from in_sizes[0]), DIM = 1280. Output fp32.
//
// Pure HBM-store-bound: 335.5 MB out, 0.25 MB in. Strategy:
//  - one thread owns one float4 column-chunk (cols 4c..4c+3 = pairs 2c, 2c+1)
//  - exp2f rates computed ONCE per thread, reused across a 32-row loop
//  - Cody-Waite reduction (exact for angle<=1000) + __sincosf on |x|<=pi
//  - fully-coalesced float4 streaming stores (__stcs)

#define DIM        1280
#define CHUNKS     (DIM / 4)      // 320 float4 per row
#define BLOCK      256
#define ROW_PAR    2048           // concurrent row lanes -> 320*2048/256 = 2560 blocks

__global__ __launch_bounds__(BLOCK)
void time_emb_kernel(const float* __restrict__ time, float4* __restrict__ out, int B)
{
    const int idx   = blockIdx.x * BLOCK + threadIdx.x;   // 0 .. 320*ROW_PAR-1
    const int chunk = idx % CHUNKS;                       // column chunk 0..319
    const int row0  = idx / CHUNKS;                       // 0..ROW_PAR-1
    const int rstride = (gridDim.x * BLOCK) / CHUNKS;     // = ROW_PAR

    // rate(p) = 10000^(-p/640) = exp2(-log2(10000)/640 * p), p = i//2
    const float C = -13.287712379549449f / 640.0f;
    const int p0 = 2 * chunk;
    const float rate0 = exp2f(C * (float)(p0));
    const float rate1 = exp2f(C * (float)(p0 + 1));

    // Cody-Waite constants: 2*pi = HI + LO, HI = 6.28125 (7 mantissa bits,
    // k <= 160 so k*HI is exact in fp32)
    const float INV2PI = 0.15915494309189535f;
    const float HI     = 6.28125f;
    const float LO     = 1.9353071795864769e-3f;

    for (int row = row0; row < B; row += rstride) {
        const float t  = __ldg(&time[row]);
        float a0 = t * rate0;
        float a1 = t * rate1;

        float k0 = rintf(a0 * INV2PI);
        float k1 = rintf(a1 * INV2PI);
        float x0 = fmaf(k0, -LO, fmaf(k0, -HI, a0));   // |x| <= pi + eps
        float x1 = fmaf(k1, -LO, fmaf(k1, -HI, a1));

        float s0, c0, s1, c1;
        __sincosf(x0, &s0, &c0);
        __sincosf(x1, &s1, &c1);

        float4 v;
        v.x = s0; v.y = c0;   // even col -> sin, odd col -> cos
        v.z = s1; v.w = c1;

        __stcs(&out[(size_t)row * CHUNKS + chunk], v);
    }
}

extern "C" void kernel_launch(void* const* d_in, const int* in_sizes, int n_in,
                              void* d_out, int out_size)
{
    const float* time = (const float*)d_in[0];
    float4* out = (float4*)d_out;
    const int B = in_sizes[0];

    const int total_threads = CHUNKS * ROW_PAR;   // 655360
    const int blocks = total_threads / BLOCK;     // 2560
    time_emb_kernel<<<blocks, BLOCK>>>(time, out, B);
}